// round 1
// baseline (speedup 1.0000x reference)
#include <cuda_runtime.h>
#include <cuda_bf16.h>
#include <math_constants.h>

// Problem constants
#define BB   512          // batch
#define T1   127          // T-1 time steps
#define EE   256          // encoder dim
#define HH   256          // hidden
#define G4   1024         // 4*H
#define NL   3            // LSTM layers
#define BH   (BB*HH)      // 131072

// ---------------- device scratch (static, no runtime alloc) ----------------
__device__ float g_encproj[(size_t)BB * T1 * EE];   // 66.6 MB
__device__ float g_qproj[BB * EE];                  // 512 KB
__device__ float g_h[2][NL * BH];                   // ping-pong hidden
__device__ float g_c[2][NL * BH];                   // ping-pong cell
__device__ float g_context[BB * EE];
__device__ float g_ytilde[BB];

// ---------------- fast math helpers ----------------
__device__ __forceinline__ float tanha(float x) {      // HW tanh (attention only)
    float r; asm("tanh.approx.f32 %0, %1;" : "=f"(r) : "f"(x)); return r;
}
__device__ __forceinline__ float ex2f(float x) {
    float r; asm("ex2.approx.f32 %0, %1;" : "=f"(r) : "f"(x)); return r;
}
__device__ __forceinline__ float rcpf(float x) {
    float r; asm("rcp.approx.f32 %0, %1;" : "=f"(r) : "f"(x)); return r;
}
// accurate-enough sigmoid / tanh for the LSTM recurrence (~1e-7 rel err)
__device__ __forceinline__ float sigf(float x) {
    return rcpf(1.0f + ex2f(-1.4426950408889634f * x));
}
__device__ __forceinline__ float tanh_ex(float x) {
    // tanh(x) = 1 - 2/(e^{2x}+1)
    float z = ex2f(2.8853900817779268f * x);
    return fmaf(-2.0f, rcpf(z + 1.0f), 1.0f);
}

// ---------------- kernel 0: zero initial state ----------------
__global__ void zero_state_kernel() {
    int i = blockIdx.x * blockDim.x + threadIdx.x;
    if (i < NL * BH) { g_h[0][i] = 0.0f; g_c[0][i] = 0.0f; }
}

// ---------------- kernel 1: enc_proj GEMM (once) ----------------
// C[m,f] = sum_e X[m,e] * W1[f, 512+e] + b1[f],  m = b*127+t  (M=65024,N=256,K=256)
// tiles: 128m x 64f, K-chunk 32, 256 threads, 8x4 micro-tile
__global__ __launch_bounds__(256) void encproj_kernel(
    const float* __restrict__ x, const float* __restrict__ w1,
    const float* __restrict__ b1)
{
    __shared__ float As[128][33];
    __shared__ float Ws[64][33];
    const int m0 = blockIdx.x * 128;
    const int f0 = blockIdx.y * 64;
    const int tid = threadIdx.x;
    const int tx = tid & 15, ty = tid >> 4;     // tx: f group, ty: m group

    float acc[8][4];
#pragma unroll
    for (int i = 0; i < 8; i++)
#pragma unroll
        for (int j = 0; j < 4; j++) acc[i][j] = 0.0f;

    for (int kc = 0; kc < 256; kc += 32) {
        // load A tile 128x32
#pragma unroll
        for (int i = tid; i < 128 * 32; i += 256) {
            int r = i >> 5, c = i & 31;
            As[r][c] = x[(size_t)(m0 + r) * 256 + kc + c];
        }
        // load W tile 64x32 (w1_e part: column offset 512)
#pragma unroll
        for (int i = tid; i < 64 * 32; i += 256) {
            int r = i >> 5, c = i & 31;
            Ws[r][c] = w1[(size_t)(f0 + r) * 768 + 512 + kc + c];
        }
        __syncthreads();
#pragma unroll 4
        for (int kk = 0; kk < 32; kk++) {
            float a[8], w[4];
#pragma unroll
            for (int i = 0; i < 8; i++) a[i] = As[ty * 8 + i][kk];
#pragma unroll
            for (int j = 0; j < 4; j++) w[j] = Ws[tx * 4 + j][kk];
#pragma unroll
            for (int i = 0; i < 8; i++)
#pragma unroll
                for (int j = 0; j < 4; j++) acc[i][j] = fmaf(a[i], w[j], acc[i][j]);
        }
        __syncthreads();
    }
#pragma unroll
    for (int j = 0; j < 4; j++) {
        float bias = b1[f0 + tx * 4 + j];
#pragma unroll
        for (int i = 0; i < 8; i++) {
            g_encproj[(size_t)(m0 + ty * 8 + i) * 256 + f0 + tx * 4 + j] = acc[i][j] + bias;
        }
    }
}

// ---------------- kernel 2: qproj GEMM (per step) ----------------
// qproj[b,f] = sum_k [h0;c0][b,k] * w1[f,k]   (M=512,N=256,K=512)
// tiles: 32b x 32f, 256 threads, 2x2 micro
__global__ __launch_bounds__(256) void qproj_kernel(const float* __restrict__ w1, int p)
{
    __shared__ float As[32][33];
    __shared__ float Ws[32][33];
    const int b0 = blockIdx.x * 32;
    const int f0 = blockIdx.y * 32;
    const int tid = threadIdx.x;
    const int tx = tid & 15, ty = tid >> 4;
    const int fl = tx * 2, bl = ty * 2;

    float acc[2][2] = {{0.f, 0.f}, {0.f, 0.f}};

    for (int kc = 0; kc < 512; kc += 32) {
        const float* S = (kc < 256) ? g_h[p] : g_c[p];   // layer 0 at offset 0
        int cof = (kc < 256) ? kc : (kc - 256);
#pragma unroll
        for (int i = tid; i < 32 * 32; i += 256) {
            int r = i >> 5, c = i & 31;
            As[r][c] = S[(b0 + r) * 256 + cof + c];
            Ws[r][c] = w1[(size_t)(f0 + r) * 768 + kc + c];
        }
        __syncthreads();
#pragma unroll 8
        for (int kk = 0; kk < 32; kk++) {
            float a0 = As[bl][kk], a1 = As[bl + 1][kk];
            float w0 = Ws[fl][kk], w1v = Ws[fl + 1][kk];
            acc[0][0] = fmaf(a0, w0, acc[0][0]);
            acc[0][1] = fmaf(a0, w1v, acc[0][1]);
            acc[1][0] = fmaf(a1, w0, acc[1][0]);
            acc[1][1] = fmaf(a1, w1v, acc[1][1]);
        }
        __syncthreads();
    }
#pragma unroll
    for (int i = 0; i < 2; i++)
#pragma unroll
        for (int j = 0; j < 2; j++)
            g_qproj[(b0 + bl + i) * 256 + f0 + fl + j] = acc[i][j];
}

// ---------------- kernel 3: attention + context + y_tilde (per step) ----------------
// one block per batch element b, 256 threads
__global__ __launch_bounds__(256) void attn_kernel(
    const float* __restrict__ x, const float* __restrict__ w2,
    const float* __restrict__ fcw, const float* __restrict__ fcb,
    const float* __restrict__ yh, int s, int p)
{
    const int b = blockIdx.x;
    const int tid = threadIdx.x;
    const int warp = tid >> 5, lane = tid & 31;

    __shared__ float s_qp[256], s_w2[256], s_sc[128];
    __shared__ float s_m[8], s_s[8], s_y[8];

    s_qp[tid] = g_qproj[b * 256 + tid];
    s_w2[tid] = w2[tid];
    __syncthreads();

    // scores[t] = sum_e w2[e]*tanh(qproj[e] + enc_proj[b,t,e])
    for (int t = warp; t < T1; t += 8) {
        const float* er = g_encproj + ((size_t)b * T1 + t) * 256;
        float ps = 0.0f;
#pragma unroll
        for (int i = 0; i < 8; i++) {
            int e = lane + i * 32;
            ps += s_w2[e] * tanha(s_qp[e] + er[e]);
        }
#pragma unroll
        for (int o = 16; o; o >>= 1) ps += __shfl_xor_sync(0xffffffffu, ps, o);
        if (lane == 0) s_sc[t] = ps;
    }
    __syncthreads();

    // softmax over 127
    float v = (tid < T1) ? s_sc[tid] : -CUDART_INF_F;
    float m = v;
#pragma unroll
    for (int o = 16; o; o >>= 1) m = fmaxf(m, __shfl_xor_sync(0xffffffffu, m, o));
    if (lane == 0) s_m[warp] = m;
    __syncthreads();
    float mx = s_m[0];
#pragma unroll
    for (int w = 1; w < 8; w++) mx = fmaxf(mx, s_m[w]);

    float e_ = (tid < T1) ? ex2f((v - mx) * 1.4426950408889634f) : 0.0f;
    float ss = e_;
#pragma unroll
    for (int o = 16; o; o >>= 1) ss += __shfl_xor_sync(0xffffffffu, ss, o);
    if (lane == 0) s_s[warp] = ss;
    if (tid < T1) s_sc[tid] = e_;
    __syncthreads();
    float total = 0.0f;
#pragma unroll
    for (int w = 0; w < 8; w++) total += s_s[w];
    float inv = 1.0f / total;

    // context[e] = sum_t alpha[t]*x[b,t,e]
    float acc = 0.0f;
    const float* xb = x + (size_t)b * T1 * 256 + tid;
#pragma unroll 4
    for (int t = 0; t < T1; t++) acc = fmaf(s_sc[t], xb[(size_t)t * 256], acc);
    acc *= inv;
    g_context[b * 256 + tid] = acc;

    // y_tilde[b] = fc_w[0:256].context + fc_w[256]*y_t + fc_b
    float yv = acc * fcw[tid];
#pragma unroll
    for (int o = 16; o; o >>= 1) yv += __shfl_xor_sync(0xffffffffu, yv, o);
    if (lane == 0) s_y[warp] = yv;
    __syncthreads();
    if (tid == 0) {
        float tot = 0.0f;
#pragma unroll
        for (int w = 0; w < 8; w++) tot += s_y[w];
        g_ytilde[b] = tot + yh[b * T1 + s] * fcw[256] + fcb[0];
    }
}

// ---------------- kernel 4: LSTM layer (per step, per layer) ----------------
// gates[b, g*256+u] = x.Wih + h.Whh + biases; tile 32b x 32u (x4 gates)
__global__ __launch_bounds__(256) void lstm_kernel(
    const float* __restrict__ wihr, const float* __restrict__ whh,
    const float* __restrict__ wih0, const float* __restrict__ bih,
    const float* __restrict__ bhh, int l, int p)
{
    __shared__ float xs[32][33];
    __shared__ float ws[4][32][33];

    const int b0 = blockIdx.x * 32;
    const int u0 = blockIdx.y * 32;
    const int tid = threadIdx.x;
    const int tx = tid & 15, ty = tid >> 4;
    const int ul = tx * 2, bl = ty * 2;

    const float* hprev = g_h[p] + l * BH;
    const float* cprev = g_c[p] + l * BH;
    const float* xsrc  = (l == 0) ? nullptr : (g_h[1 - p] + (l - 1) * BH);
    const float* Whh   = whh + (size_t)l * G4 * HH;
    const float* Wih   = (l == 0) ? nullptr : (wihr + (size_t)(l - 1) * G4 * HH);

    float acc[2][2][4];
#pragma unroll
    for (int i = 0; i < 2; i++)
#pragma unroll
        for (int j = 0; j < 2; j++)
#pragma unroll
            for (int g = 0; g < 4; g++) acc[i][j][g] = 0.0f;

    const int npass = (l == 0) ? 1 : 2;
    for (int pass = 0; pass < npass; pass++) {
        const float* S = pass ? xsrc : hprev;
        const float* W = pass ? Wih : Whh;
        for (int kc = 0; kc < 256; kc += 32) {
#pragma unroll
            for (int i = tid; i < 32 * 32; i += 256) {
                int r = i >> 5, c = i & 31;
                xs[r][c] = S[(b0 + r) * 256 + kc + c];
            }
#pragma unroll
            for (int i = tid; i < 4 * 32 * 32; i += 256) {
                int g = i >> 10, rem = i & 1023;
                int u = rem >> 5, c = rem & 31;
                ws[g][u][c] = W[(size_t)((g << 8) + u0 + u) * 256 + kc + c];
            }
            __syncthreads();
#pragma unroll 4
            for (int kk = 0; kk < 32; kk++) {
                float a0 = xs[bl][kk], a1 = xs[bl + 1][kk];
#pragma unroll
                for (int g = 0; g < 4; g++) {
                    float w0 = ws[g][ul][kk], w1 = ws[g][ul + 1][kk];
                    acc[0][0][g] = fmaf(a0, w0, acc[0][0][g]);
                    acc[0][1][g] = fmaf(a0, w1, acc[0][1][g]);
                    acc[1][0][g] = fmaf(a1, w0, acc[1][0][g]);
                    acc[1][1][g] = fmaf(a1, w1, acc[1][1][g]);
                }
            }
            __syncthreads();
        }
    }

    // epilogue: gate nonlinearities + state update
#pragma unroll
    for (int i = 0; i < 2; i++) {
#pragma unroll
        for (int j = 0; j < 2; j++) {
            int b = b0 + bl + i;
            int u = u0 + ul + j;
            float gi = acc[i][j][0] + bih[l * G4 + 0 * 256 + u] + bhh[l * G4 + 0 * 256 + u];
            float gf = acc[i][j][1] + bih[l * G4 + 1 * 256 + u] + bhh[l * G4 + 1 * 256 + u];
            float gg = acc[i][j][2] + bih[l * G4 + 2 * 256 + u] + bhh[l * G4 + 2 * 256 + u];
            float go = acc[i][j][3] + bih[l * G4 + 3 * 256 + u] + bhh[l * G4 + 3 * 256 + u];
            if (l == 0) {
                float yt = g_ytilde[b];
                gi = fmaf(yt, wih0[0 * 256 + u], gi);
                gf = fmaf(yt, wih0[1 * 256 + u], gf);
                gg = fmaf(yt, wih0[2 * 256 + u], gg);
                go = fmaf(yt, wih0[3 * 256 + u], go);
            }
            float co = cprev[b * 256 + u];
            float cn = sigf(gf) * co + sigf(gi) * tanh_ex(gg);
            float hn = sigf(go) * tanh_ex(cn);
            g_c[1 - p][l * BH + b * 256 + u] = cn;
            g_h[1 - p][l * BH + b * 256 + u] = hn;
        }
    }
}

// ---------------- kernel 5: final projection ----------------
// y_pred[b] = fcf_w[0:256].h_final0[b] + fcf_w[256:512].context[b] + fcf_b
__global__ __launch_bounds__(256) void final_kernel(
    const float* __restrict__ fcfw, const float* __restrict__ fcfb,
    float* __restrict__ out)
{
    const int b = blockIdx.x;
    const int tid = threadIdx.x;
    const int warp = tid >> 5, lane = tid & 31;
    __shared__ float s_r[8];

    // final state parity: after 127 steps last write went to parity 1
    float v = g_h[1][0 * BH + b * 256 + tid] * fcfw[tid]
            + g_context[b * 256 + tid] * fcfw[256 + tid];
#pragma unroll
    for (int o = 16; o; o >>= 1) v += __shfl_xor_sync(0xffffffffu, v, o);
    if (lane == 0) s_r[warp] = v;
    __syncthreads();
    if (tid == 0) {
        float tot = 0.0f;
#pragma unroll
        for (int w = 0; w < 8; w++) tot += s_r[w];
        out[b] = tot + fcfb[0];
    }
}

// ---------------- host launcher ----------------
extern "C" void kernel_launch(void* const* d_in, const int* in_sizes, int n_in,
                              void* d_out, int out_size)
{
    const float* x    = (const float*)d_in[0];   // input_encoded (512,127,256)
    const float* yh   = (const float*)d_in[1];   // y_history (512,127)
    const float* w1   = (const float*)d_in[2];   // attn_w1 (256,768)
    const float* b1   = (const float*)d_in[3];   // attn_b1 (256)
    const float* w2   = (const float*)d_in[4];   // attn_w2 (1,256)
    // d_in[5] attn_b2: softmax-invariant constant, unused
    const float* wih0 = (const float*)d_in[6];   // (1024,1)
    const float* wihr = (const float*)d_in[7];   // (2,1024,256)
    const float* whh  = (const float*)d_in[8];   // (3,1024,256)
    const float* bih  = (const float*)d_in[9];   // (3,1024)
    const float* bhh  = (const float*)d_in[10];  // (3,1024)
    const float* fcw  = (const float*)d_in[11];  // (1,257)
    const float* fcb  = (const float*)d_in[12];  // (1)
    const float* fcfw = (const float*)d_in[13];  // (1,512)
    const float* fcfb = (const float*)d_in[14];  // (1)
    float* out = (float*)d_out;

    zero_state_kernel<<<(NL * BH + 255) / 256, 256>>>();
    encproj_kernel<<<dim3(508, 4), 256>>>(x, w1, b1);

    for (int s = 0; s < T1; s++) {
        int p = s & 1;
        qproj_kernel<<<dim3(16, 8), 256>>>(w1, p);
        attn_kernel<<<BB, 256>>>(x, w2, fcw, fcb, yh, s, p);
        for (int l = 0; l < NL; l++)
            lstm_kernel<<<dim3(16, 8), 256>>>(wihr, whh, wih0, bih, bhh, l, p);
    }

    final_kernel<<<BB, 256>>>(fcfw, fcfb, out);
}

// round 2
// speedup vs baseline: 1.0058x; 1.0058x over previous
#include <cuda_runtime.h>
#include <cuda_bf16.h>
#include <math_constants.h>

// Problem constants
#define BB   512          // batch
#define T1   127          // T-1 time steps
#define EE   256          // encoder dim
#define HH   256          // hidden
#define G4   1024         // 4*H
#define NL   3            // LSTM layers
#define BH   (BB*HH)      // 131072

// ---------------- device scratch (static, no runtime alloc) ----------------
__device__ __nv_bfloat16 g_encproj_bf[(size_t)BB * T1 * EE];  // 33.3 MB
__device__ float g_qproj[BB * EE];
__device__ float g_h[2][NL * BH];
__device__ float g_c[2][NL * BH];
__device__ float g_context[BB * EE];
__device__ float g_ytilde[BB];

// ---------------- fast math helpers ----------------
__device__ __forceinline__ float tanha(float x) {      // HW tanh (attention only)
    float r; asm("tanh.approx.f32 %0, %1;" : "=f"(r) : "f"(x)); return r;
}
__device__ __forceinline__ float ex2f(float x) {
    float r; asm("ex2.approx.f32 %0, %1;" : "=f"(r) : "f"(x)); return r;
}
__device__ __forceinline__ float rcpf(float x) {
    float r; asm("rcp.approx.f32 %0, %1;" : "=f"(r) : "f"(x)); return r;
}
__device__ __forceinline__ float sigf(float x) {
    return rcpf(1.0f + ex2f(-1.4426950408889634f * x));
}
__device__ __forceinline__ float tanh_ex(float x) {
    float z = ex2f(2.8853900817779268f * x);
    return fmaf(-2.0f, rcpf(z + 1.0f), 1.0f);
}

// packed 2-wide fp32 FMA (FFMA2) — exact fp32 numerics, 2x issue rate
__device__ __forceinline__ float2 ffma2(float2 a, float2 b, float2 c) {
    union U { float2 f; unsigned long long u; };
    U ua, ub, uc, ud;
    ua.f = a; ub.f = b; uc.f = c;
    asm("fma.rn.f32x2 %0, %1, %2, %3;" : "=l"(ud.u) : "l"(ua.u), "l"(ub.u), "l"(uc.u));
    return ud.f;
}

// ---------------- kernel 0: zero initial state ----------------
__global__ void zero_state_kernel() {
    int i = blockIdx.x * blockDim.x + threadIdx.x;
    if (i < NL * BH) { g_h[0][i] = 0.0f; g_c[0][i] = 0.0f; }
}

// ---------------- kernel 1: enc_proj GEMM (once), bf16 output ----------------
// C[m,f] = sum_e X[m,e] * W1[f, 512+e] + b1[f],  m = b*127+t  (M=65024,N=256,K=256)
__global__ __launch_bounds__(256) void encproj_kernel(
    const float* __restrict__ x, const float* __restrict__ w1,
    const float* __restrict__ b1)
{
    __shared__ float As[128][33];
    __shared__ float Ws[64][33];
    const int m0 = blockIdx.x * 128;
    const int f0 = blockIdx.y * 64;
    const int tid = threadIdx.x;
    const int tx = tid & 15, ty = tid >> 4;

    float acc[8][4];
#pragma unroll
    for (int i = 0; i < 8; i++)
#pragma unroll
        for (int j = 0; j < 4; j++) acc[i][j] = 0.0f;

    for (int kc = 0; kc < 256; kc += 32) {
#pragma unroll
        for (int i = tid; i < 128 * 32; i += 256) {
            int r = i >> 5, c = i & 31;
            As[r][c] = x[(size_t)(m0 + r) * 256 + kc + c];
        }
#pragma unroll
        for (int i = tid; i < 64 * 32; i += 256) {
            int r = i >> 5, c = i & 31;
            Ws[r][c] = w1[(size_t)(f0 + r) * 768 + 512 + kc + c];
        }
        __syncthreads();
#pragma unroll 4
        for (int kk = 0; kk < 32; kk++) {
            float a[8], w[4];
#pragma unroll
            for (int i = 0; i < 8; i++) a[i] = As[ty * 8 + i][kk];
#pragma unroll
            for (int j = 0; j < 4; j++) w[j] = Ws[tx * 4 + j][kk];
#pragma unroll
            for (int i = 0; i < 8; i++)
#pragma unroll
                for (int j = 0; j < 4; j++) acc[i][j] = fmaf(a[i], w[j], acc[i][j]);
        }
        __syncthreads();
    }
#pragma unroll
    for (int j = 0; j < 4; j++) {
        float bias = b1[f0 + tx * 4 + j];
#pragma unroll
        for (int i = 0; i < 8; i++) {
            g_encproj_bf[(size_t)(m0 + ty * 8 + i) * 256 + f0 + tx * 4 + j] =
                __float2bfloat16_rn(acc[i][j] + bias);
        }
    }
}

// ---------------- kernel 2: qproj GEMM (per step), packed f32x2 ----------------
// qproj[b,f] = sum_k [h0;c0][b,k] * w1[f,k]   (M=512,N=256,K=512)
__global__ __launch_bounds__(256) void qproj_kernel(const float* __restrict__ w1, int p)
{
    __shared__ float xs[32][34];   // [kk][b]
    __shared__ float ws[32][34];   // [kk][f]
    const int b0 = blockIdx.x * 32;
    const int f0 = blockIdx.y * 32;
    const int tid = threadIdx.x;
    const int tx = tid & 15, ty = tid >> 4;
    const int fl = tx * 2, bl = ty * 2;

    float2 acc[2];
    acc[0] = make_float2(0.f, 0.f);
    acc[1] = make_float2(0.f, 0.f);

    const int ldb = tid >> 3, ldk = (tid & 7) * 4;   // state loader: row b, 4 k's
    for (int kc = 0; kc < 512; kc += 32) {
        const float* S = (kc < 256) ? g_h[p] : g_c[p];
        int cof = (kc < 256) ? kc : (kc - 256);
        {
            float4 v = *(const float4*)&S[(b0 + ldb) * 256 + cof + ldk];
            xs[ldk + 0][ldb] = v.x; xs[ldk + 1][ldb] = v.y;
            xs[ldk + 2][ldb] = v.z; xs[ldk + 3][ldb] = v.w;
        }
        {
            float4 v = *(const float4*)&w1[(size_t)(f0 + ldb) * 768 + kc + ldk];
            ws[ldk + 0][ldb] = v.x; ws[ldk + 1][ldb] = v.y;
            ws[ldk + 2][ldb] = v.z; ws[ldk + 3][ldb] = v.w;
        }
        __syncthreads();
#pragma unroll
        for (int kk = 0; kk < 32; kk++) {
            float2 a = *(const float2*)&xs[kk][bl];
            float2 w = *(const float2*)&ws[kk][fl];
            acc[0] = ffma2(make_float2(a.x, a.x), w, acc[0]);
            acc[1] = ffma2(make_float2(a.y, a.y), w, acc[1]);
        }
        __syncthreads();
    }
    g_qproj[(b0 + bl + 0) * 256 + f0 + fl + 0] = acc[0].x;
    g_qproj[(b0 + bl + 0) * 256 + f0 + fl + 1] = acc[0].y;
    g_qproj[(b0 + bl + 1) * 256 + f0 + fl + 0] = acc[1].x;
    g_qproj[(b0 + bl + 1) * 256 + f0 + fl + 1] = acc[1].y;
}

// ---------------- kernel 3: attention + context + y_tilde (per step) ----------------
// one block per batch element b; scores read bf16 enc_proj, context reads fp32 x
__global__ __launch_bounds__(256) void attn_kernel(
    const float* __restrict__ x, const float* __restrict__ w2,
    const float* __restrict__ fcw, const float* __restrict__ fcb,
    const float* __restrict__ yh, int s, int p)
{
    const int b = blockIdx.x;
    const int tid = threadIdx.x;
    const int warp = tid >> 5, lane = tid & 31;

    __shared__ float s_qp[256], s_w2[256], s_sc[128];
    __shared__ float s_m[8], s_s[8], s_y[8];

    s_qp[tid] = g_qproj[b * 256 + tid];
    s_w2[tid] = w2[tid];
    __syncthreads();

    // scores[t] = sum_e w2[e]*tanh(qproj[e] + enc_proj[b,t,e])
    for (int t = warp; t < T1; t += 8) {
        const __nv_bfloat162* er =
            (const __nv_bfloat162*)(g_encproj_bf + ((size_t)b * T1 + t) * 256);
        float ps = 0.0f;
#pragma unroll
        for (int i = 0; i < 4; i++) {
            int e2 = lane + i * 32;           // pair index 0..127
            float2 ev = __bfloat1622float2(er[e2]);
            int e = e2 * 2;
            ps += s_w2[e]     * tanha(s_qp[e]     + ev.x);
            ps += s_w2[e + 1] * tanha(s_qp[e + 1] + ev.y);
        }
#pragma unroll
        for (int o = 16; o; o >>= 1) ps += __shfl_xor_sync(0xffffffffu, ps, o);
        if (lane == 0) s_sc[t] = ps;
    }
    __syncthreads();

    // softmax over 127
    float v = (tid < T1) ? s_sc[tid] : -CUDART_INF_F;
    float m = v;
#pragma unroll
    for (int o = 16; o; o >>= 1) m = fmaxf(m, __shfl_xor_sync(0xffffffffu, m, o));
    if (lane == 0) s_m[warp] = m;
    __syncthreads();
    float mx = s_m[0];
#pragma unroll
    for (int w = 1; w < 8; w++) mx = fmaxf(mx, s_m[w]);

    float e_ = (tid < T1) ? ex2f((v - mx) * 1.4426950408889634f) : 0.0f;
    float ss = e_;
#pragma unroll
    for (int o = 16; o; o >>= 1) ss += __shfl_xor_sync(0xffffffffu, ss, o);
    if (lane == 0) s_s[warp] = ss;
    if (tid < T1) s_sc[tid] = e_;
    __syncthreads();
    float total = 0.0f;
#pragma unroll
    for (int w = 0; w < 8; w++) total += s_s[w];
    float inv = 1.0f / total;

    // context[e] = sum_t alpha[t]*x[b,t,e]   (fp32 x for accuracy)
    float acc = 0.0f;
    const float* xb = x + (size_t)b * T1 * 256 + tid;
#pragma unroll 4
    for (int t = 0; t < T1; t++) acc = fmaf(s_sc[t], xb[(size_t)t * 256], acc);
    acc *= inv;
    g_context[b * 256 + tid] = acc;

    // y_tilde[b] = fc_w[0:256].context + fc_w[256]*y_t + fc_b
    float yv = acc * fcw[tid];
#pragma unroll
    for (int o = 16; o; o >>= 1) yv += __shfl_xor_sync(0xffffffffu, yv, o);
    if (lane == 0) s_y[warp] = yv;
    __syncthreads();
    if (tid == 0) {
        float tot = 0.0f;
#pragma unroll
        for (int w = 0; w < 8; w++) tot += s_y[w];
        g_ytilde[b] = tot + yh[b * T1 + s] * fcw[256] + fcb[0];
    }
}

// ---------------- kernel 4: LSTM layer (per step, per layer), packed f32x2 ----------------
// gates[b, g*256+u] = x.Wih + h.Whh + biases; tile 32b x 32u x 4g, micro 2b x 2u(packed) x 4g
__global__ __launch_bounds__(256) void lstm_kernel(
    const float* __restrict__ wihr, const float* __restrict__ whh,
    const float* __restrict__ wih0, const float* __restrict__ bih,
    const float* __restrict__ bhh, int l, int p)
{
    __shared__ float xs[32][34];        // [kk][b]
    __shared__ float ws[4][32][34];     // [g][kk][u]

    const int b0 = blockIdx.x * 32;
    const int u0 = blockIdx.y * 32;
    const int tid = threadIdx.x;
    const int tx = tid & 15, ty = tid >> 4;
    const int ul = tx * 2, bl = ty * 2;

    const float* hprev = g_h[p] + l * BH;
    const float* cprev = g_c[p] + l * BH;
    const float* xsrc  = (l == 0) ? nullptr : (g_h[1 - p] + (l - 1) * BH);
    const float* Whh   = whh + (size_t)l * G4 * HH;
    const float* Wih   = (l == 0) ? nullptr : (wihr + (size_t)(l - 1) * G4 * HH);

    float2 acc[2][4];                   // [bi][g], packed along u
#pragma unroll
    for (int i = 0; i < 2; i++)
#pragma unroll
        for (int g = 0; g < 4; g++) acc[i][g] = make_float2(0.f, 0.f);

    const int ldb = tid >> 3, ldk = (tid & 7) * 4;   // state loader
    const int npass = (l == 0) ? 1 : 2;
    for (int pass = 0; pass < npass; pass++) {
        const float* S = pass ? xsrc : hprev;
        const float* W = pass ? Wih : Whh;
        for (int kc = 0; kc < 256; kc += 32) {
            // state tile 32b x 32k, transposed into xs[kk][b]
            {
                float4 v = *(const float4*)&S[(b0 + ldb) * 256 + kc + ldk];
                xs[ldk + 0][ldb] = v.x; xs[ldk + 1][ldb] = v.y;
                xs[ldk + 2][ldb] = v.z; xs[ldk + 3][ldb] = v.w;
            }
            // weight tiles: 4 gates x 32u x 32k, transposed into ws[g][kk][u]
#pragma unroll
            for (int i = tid; i < 1024; i += 256) {
                int g = i >> 8, u = (i >> 3) & 31, kq = (i & 7) * 4;
                float4 v = *(const float4*)&W[(size_t)((g << 8) + u0 + u) * 256 + kc + kq];
                ws[g][kq + 0][u] = v.x; ws[g][kq + 1][u] = v.y;
                ws[g][kq + 2][u] = v.z; ws[g][kq + 3][u] = v.w;
            }
            __syncthreads();
#pragma unroll
            for (int kk = 0; kk < 32; kk++) {
                float2 a = *(const float2*)&xs[kk][bl];
                float2 a0 = make_float2(a.x, a.x);
                float2 a1 = make_float2(a.y, a.y);
#pragma unroll
                for (int g = 0; g < 4; g++) {
                    float2 w = *(const float2*)&ws[g][kk][ul];
                    acc[0][g] = ffma2(a0, w, acc[0][g]);
                    acc[1][g] = ffma2(a1, w, acc[1][g]);
                }
            }
            __syncthreads();
        }
    }

    // epilogue: gate nonlinearities + state update
#pragma unroll
    for (int i = 0; i < 2; i++) {
#pragma unroll
        for (int j = 0; j < 2; j++) {
            int b = b0 + bl + i;
            int u = u0 + ul + j;
            float gi = (j ? acc[i][0].y : acc[i][0].x) + bih[l * G4 + 0 * 256 + u] + bhh[l * G4 + 0 * 256 + u];
            float gf = (j ? acc[i][1].y : acc[i][1].x) + bih[l * G4 + 1 * 256 + u] + bhh[l * G4 + 1 * 256 + u];
            float gg = (j ? acc[i][2].y : acc[i][2].x) + bih[l * G4 + 2 * 256 + u] + bhh[l * G4 + 2 * 256 + u];
            float go = (j ? acc[i][3].y : acc[i][3].x) + bih[l * G4 + 3 * 256 + u] + bhh[l * G4 + 3 * 256 + u];
            if (l == 0) {
                float yt = g_ytilde[b];
                gi = fmaf(yt, wih0[0 * 256 + u], gi);
                gf = fmaf(yt, wih0[1 * 256 + u], gf);
                gg = fmaf(yt, wih0[2 * 256 + u], gg);
                go = fmaf(yt, wih0[3 * 256 + u], go);
            }
            float co = cprev[b * 256 + u];
            float cn = sigf(gf) * co + sigf(gi) * tanh_ex(gg);
            float hn = sigf(go) * tanh_ex(cn);
            g_c[1 - p][l * BH + b * 256 + u] = cn;
            g_h[1 - p][l * BH + b * 256 + u] = hn;
        }
    }
}

// ---------------- kernel 5: final projection ----------------
__global__ __launch_bounds__(256) void final_kernel(
    const float* __restrict__ fcfw, const float* __restrict__ fcfb,
    float* __restrict__ out)
{
    const int b = blockIdx.x;
    const int tid = threadIdx.x;
    const int warp = tid >> 5, lane = tid & 31;
    __shared__ float s_r[8];

    float v = g_h[1][0 * BH + b * 256 + tid] * fcfw[tid]
            + g_context[b * 256 + tid] * fcfw[256 + tid];
#pragma unroll
    for (int o = 16; o; o >>= 1) v += __shfl_xor_sync(0xffffffffu, v, o);
    if (lane == 0) s_r[warp] = v;
    __syncthreads();
    if (tid == 0) {
        float tot = 0.0f;
#pragma unroll
        for (int w = 0; w < 8; w++) tot += s_r[w];
        out[b] = tot + fcfb[0];
    }
}

// ---------------- host launcher ----------------
extern "C" void kernel_launch(void* const* d_in, const int* in_sizes, int n_in,
                              void* d_out, int out_size)
{
    const float* x    = (const float*)d_in[0];
    const float* yh   = (const float*)d_in[1];
    const float* w1   = (const float*)d_in[2];
    const float* b1   = (const float*)d_in[3];
    const float* w2   = (const float*)d_in[4];
    const float* wih0 = (const float*)d_in[6];
    const float* wihr = (const float*)d_in[7];
    const float* whh  = (const float*)d_in[8];
    const float* bih  = (const float*)d_in[9];
    const float* bhh  = (const float*)d_in[10];
    const float* fcw  = (const float*)d_in[11];
    const float* fcb  = (const float*)d_in[12];
    const float* fcfw = (const float*)d_in[13];
    const float* fcfb = (const float*)d_in[14];
    float* out = (float*)d_out;

    zero_state_kernel<<<(NL * BH + 255) / 256, 256>>>();
    encproj_kernel<<<dim3(508, 4), 256>>>(x, w1, b1);

    for (int s = 0; s < T1; s++) {
        int p = s & 1;
        qproj_kernel<<<dim3(16, 8), 256>>>(w1, p);
        attn_kernel<<<BB, 256>>>(x, w2, fcw, fcb, yh, s, p);
        for (int l = 0; l < NL; l++)
            lstm_kernel<<<dim3(16, 8), 256>>>(wihr, whh, wih0, bih, bhh, l, p);
    }

    final_kernel<<<BB, 256>>>(fcfw, fcfb, out);
}

// round 3
// speedup vs baseline: 1.3802x; 1.3724x over previous
#include <cuda_runtime.h>
#include <cuda_bf16.h>
#include <math_constants.h>

// Problem constants
#define BB   512          // batch
#define T1   127          // T-1 time steps
#define EE   256          // encoder dim
#define HH   256          // hidden
#define G4   1024         // 4*H
#define NL   3            // LSTM layers
#define BH   (BB*HH)      // 131072

// ---------------- device scratch ----------------
__device__ __nv_bfloat16 g_encproj_bf[(size_t)BB * T1 * EE];  // 33.3 MB
__device__ float g_qproj[BB * EE];
__device__ float g_scores[BB * 128];
__device__ float g_gates[(size_t)NL * BB * G4];    // Whh-part + biases
__device__ float g_h[NL * BH];
__device__ float g_c[NL * BH];
__device__ float g_context[BB * EE];
__device__ float g_ytilde[BB];

// ---------------- fast math helpers ----------------
__device__ __forceinline__ float tanha(float x) {
    float r; asm("tanh.approx.f32 %0, %1;" : "=f"(r) : "f"(x)); return r;
}
__device__ __forceinline__ float ex2f(float x) {
    float r; asm("ex2.approx.f32 %0, %1;" : "=f"(r) : "f"(x)); return r;
}
__device__ __forceinline__ float rcpf(float x) {
    float r; asm("rcp.approx.f32 %0, %1;" : "=f"(r) : "f"(x)); return r;
}
__device__ __forceinline__ float sigf(float x) {
    return rcpf(1.0f + ex2f(-1.4426950408889634f * x));
}
__device__ __forceinline__ float tanh_ex(float x) {
    float z = ex2f(2.8853900817779268f * x);
    return fmaf(-2.0f, rcpf(z + 1.0f), 1.0f);
}
// packed 2-wide fp32 FMA (FFMA2) — exact fp32 numerics, 2x issue rate
__device__ __forceinline__ float2 ffma2(float2 a, float2 b, float2 c) {
    union U { float2 f; unsigned long long u; };
    U ua, ub, uc, ud;
    ua.f = a; ub.f = b; uc.f = c;
    asm("fma.rn.f32x2 %0, %1, %2, %3;" : "=l"(ud.u) : "l"(ua.u), "l"(ub.u), "l"(uc.u));
    return ud.f;
}

// ---------------- 64x64 tile GEMM core (micro 4x4, f32x2) ----------------
// smem tiles transposed: As[kk][row], Ws[kk][col], padded to 68
__device__ __forceinline__ void mm64_inner(const float (*As)[68], const float (*Ws)[68],
                                           float2 acc[4][2], int tx, int ty)
{
#pragma unroll
    for (int kk = 0; kk < 32; kk++) {
        float4 a = *(const float4*)&As[kk][ty * 4];
        float4 w = *(const float4*)&Ws[kk][tx * 4];
        float2 wlo = make_float2(w.x, w.y), whi = make_float2(w.z, w.w);
        acc[0][0] = ffma2(make_float2(a.x, a.x), wlo, acc[0][0]);
        acc[0][1] = ffma2(make_float2(a.x, a.x), whi, acc[0][1]);
        acc[1][0] = ffma2(make_float2(a.y, a.y), wlo, acc[1][0]);
        acc[1][1] = ffma2(make_float2(a.y, a.y), whi, acc[1][1]);
        acc[2][0] = ffma2(make_float2(a.z, a.z), wlo, acc[2][0]);
        acc[2][1] = ffma2(make_float2(a.z, a.z), whi, acc[2][1]);
        acc[3][0] = ffma2(make_float2(a.w, a.w), wlo, acc[3][0]);
        acc[3][1] = ffma2(make_float2(a.w, a.w), whi, acc[3][1]);
    }
}

#define TILE_WR(dst, v0, v1, kq, r) \
    dst[(kq)+0][r]=v0.x; dst[(kq)+1][r]=v0.y; dst[(kq)+2][r]=v0.z; dst[(kq)+3][r]=v0.w; \
    dst[(kq)+4][r]=v1.x; dst[(kq)+5][r]=v1.y; dst[(kq)+6][r]=v1.z; dst[(kq)+7][r]=v1.w;

// ---------------- kernel 0: zero initial state ----------------
__global__ void zero_state_kernel() {
    int i = blockIdx.x * blockDim.x + threadIdx.x;
    if (i < NL * BH) { g_h[i] = 0.0f; g_c[i] = 0.0f; }
}

// ---------------- kernel 1: enc_proj GEMM (once), bf16 output ----------------
// C[m,f] = sum_e X[m,e]*W1[f,512+e] + b1[f]  (M=65024, N=256, K=256)
__global__ __launch_bounds__(256) void encproj_kernel(
    const float* __restrict__ x, const float* __restrict__ w1,
    const float* __restrict__ b1)
{
    __shared__ float As[32][68];
    __shared__ float Ws[32][68];
    const int m0 = blockIdx.x * 64;
    const int f0 = blockIdx.y * 64;
    const int tid = threadIdx.x;
    const int tx = tid & 15, ty = tid >> 4;
    const int rl = tid & 63, kq = (tid >> 6) * 8;

    float2 acc[4][2];
#pragma unroll
    for (int i = 0; i < 4; i++) { acc[i][0] = make_float2(0.f, 0.f); acc[i][1] = make_float2(0.f, 0.f); }

    for (int kc = 0; kc < 256; kc += 32) {
        const float* sp = &x[(size_t)(m0 + rl) * 256 + kc + kq];
        float4 v0 = *(const float4*)sp, v1 = *(const float4*)(sp + 4);
        const float* wp = &w1[(size_t)(f0 + rl) * 768 + 512 + kc + kq];
        float4 u0 = *(const float4*)wp, u1 = *(const float4*)(wp + 4);
        TILE_WR(As, v0, v1, kq, rl);
        TILE_WR(Ws, u0, u1, kq, rl);
        __syncthreads();
        mm64_inner(As, Ws, acc, tx, ty);
        __syncthreads();
    }

    float4 bias = *(const float4*)&b1[f0 + tx * 4];
#pragma unroll
    for (int i = 0; i < 4; i++) {
        __nv_bfloat162 p0, p1;
        p0.x = __float2bfloat16_rn(acc[i][0].x + bias.x);
        p0.y = __float2bfloat16_rn(acc[i][0].y + bias.y);
        p1.x = __float2bfloat16_rn(acc[i][1].x + bias.z);
        p1.y = __float2bfloat16_rn(acc[i][1].y + bias.w);
        __nv_bfloat162* dst = (__nv_bfloat162*)&g_encproj_bf[(size_t)(m0 + ty * 4 + i) * 256 + f0 + tx * 4];
        dst[0] = p0; dst[1] = p1;
    }
}

// ---------------- kernel K1: fused qproj + Whh-gates (per step) ----------------
// blocks 0..31: qproj[b,f] = [h0;c0] @ w1_q^T   (M=512,N=256,K=512)
// blocks 32..415: gates_whh[l][b][gu] = h[l] @ Whh[l]^T + bih + bhh
__global__ __launch_bounds__(256) void fused_gemm_kernel(
    const float* __restrict__ w1, const float* __restrict__ whh,
    const float* __restrict__ bih, const float* __restrict__ bhh)
{
    __shared__ float As[32][68];
    __shared__ float Ws[32][68];
    const int tid = threadIdx.x;
    const int tx = tid & 15, ty = tid >> 4;
    const int rl = tid & 63, kq = (tid >> 6) * 8;
    const int bid = blockIdx.x;

    float2 acc[4][2];
#pragma unroll
    for (int i = 0; i < 4; i++) { acc[i][0] = make_float2(0.f, 0.f); acc[i][1] = make_float2(0.f, 0.f); }

    if (bid < 32) {
        const int b0 = (bid & 7) * 64, f0 = (bid >> 3) * 64;
#pragma unroll
        for (int pass = 0; pass < 2; pass++) {
            const float* S = pass ? g_c : g_h;   // layer 0 slices at offset 0
            for (int kc = 0; kc < 256; kc += 32) {
                const float* sp = &S[(size_t)(b0 + rl) * 256 + kc + kq];
                float4 v0 = *(const float4*)sp, v1 = *(const float4*)(sp + 4);
                const float* wp = &w1[(size_t)(f0 + rl) * 768 + pass * 256 + kc + kq];
                float4 u0 = *(const float4*)wp, u1 = *(const float4*)(wp + 4);
                TILE_WR(As, v0, v1, kq, rl);
                TILE_WR(Ws, u0, u1, kq, rl);
                __syncthreads();
                mm64_inner(As, Ws, acc, tx, ty);
                __syncthreads();
            }
        }
#pragma unroll
        for (int i = 0; i < 4; i++) {
            float4 o = make_float4(acc[i][0].x, acc[i][0].y, acc[i][1].x, acc[i][1].y);
            *(float4*)&g_qproj[(b0 + ty * 4 + i) * 256 + f0 + tx * 4] = o;
        }
    } else {
        const int w = bid - 32;
        const int l = w >> 7;
        const int r = w & 127;
        const int b0 = (r & 7) * 64, gu0 = (r >> 3) * 64;
        const float* S = g_h + l * BH;
        const float* W = whh + (size_t)l * G4 * HH;
        for (int kc = 0; kc < 256; kc += 32) {
            const float* sp = &S[(size_t)(b0 + rl) * 256 + kc + kq];
            float4 v0 = *(const float4*)sp, v1 = *(const float4*)(sp + 4);
            const float* wp = &W[(size_t)(gu0 + rl) * 256 + kc + kq];
            float4 u0 = *(const float4*)wp, u1 = *(const float4*)(wp + 4);
            TILE_WR(As, v0, v1, kq, rl);
            TILE_WR(Ws, u0, u1, kq, rl);
            __syncthreads();
            mm64_inner(As, Ws, acc, tx, ty);
            __syncthreads();
        }
        const int gu = gu0 + tx * 4;
        float4 bb1 = *(const float4*)&bih[l * G4 + gu];
        float4 bb2 = *(const float4*)&bhh[l * G4 + gu];
#pragma unroll
        for (int i = 0; i < 4; i++) {
            float4 o = make_float4(acc[i][0].x + bb1.x + bb2.x,
                                   acc[i][0].y + bb1.y + bb2.y,
                                   acc[i][1].x + bb1.z + bb2.z,
                                   acc[i][1].y + bb1.w + bb2.w);
            *(float4*)&g_gates[((size_t)l * BB + b0 + ty * 4 + i) * G4 + gu] = o;
        }
    }
}

// ---------------- kernel K2: attention scores (per step) ----------------
// scores[b,t] = sum_e w2[e]*tanh(qproj[b,e] + enc_proj[b,t,e]);  grid (512, 4)
__global__ __launch_bounds__(256) void scores_kernel(const float* __restrict__ w2)
{
    const int b = blockIdx.x;
    const int tq = blockIdx.y;
    const int tid = threadIdx.x;
    const int warp = tid >> 5, lane = tid & 31;

    __shared__ float s_qp[256], s_w2[256];
    s_qp[tid] = g_qproj[b * 256 + tid];
    s_w2[tid] = w2[tid];
    __syncthreads();

#pragma unroll
    for (int tl = warp; tl < 32; tl += 8) {
        int t = tq * 32 + tl;
        if (t < T1) {
            const __nv_bfloat162* er =
                (const __nv_bfloat162*)(g_encproj_bf + ((size_t)b * T1 + t) * 256);
            float ps = 0.0f;
#pragma unroll
            for (int i = 0; i < 4; i++) {
                int e2 = lane + i * 32;
                float2 ev = __bfloat1622float2(er[e2]);
                int e = e2 * 2;
                ps += s_w2[e]     * tanha(s_qp[e]     + ev.x);
                ps += s_w2[e + 1] * tanha(s_qp[e + 1] + ev.y);
            }
#pragma unroll
            for (int o = 16; o; o >>= 1) ps += __shfl_xor_sync(0xffffffffu, ps, o);
            if (lane == 0) g_scores[b * 128 + t] = ps;
        }
    }
}

// ---------------- kernel K3: softmax + context + y_tilde + LSTM-0 pointwise ----------------
__global__ __launch_bounds__(256) void attn_finish_kernel(
    const float* __restrict__ x, const float* __restrict__ fcw,
    const float* __restrict__ fcb, const float* __restrict__ yh,
    const float* __restrict__ wih0, int s)
{
    const int b = blockIdx.x;
    const int tid = threadIdx.x;
    const int warp = tid >> 5, lane = tid & 31;

    __shared__ float s_sc[128];
    __shared__ float s_m[8], s_s[8], s_y[8];
    __shared__ float s_yt;

    // softmax over 127 scores
    float v = (tid < T1) ? g_scores[b * 128 + tid] : -CUDART_INF_F;
    float m = v;
#pragma unroll
    for (int o = 16; o; o >>= 1) m = fmaxf(m, __shfl_xor_sync(0xffffffffu, m, o));
    if (lane == 0) s_m[warp] = m;
    __syncthreads();
    float mx = s_m[0];
#pragma unroll
    for (int w = 1; w < 8; w++) mx = fmaxf(mx, s_m[w]);

    float e_ = (tid < T1) ? ex2f((v - mx) * 1.4426950408889634f) : 0.0f;
    float ss = e_;
#pragma unroll
    for (int o = 16; o; o >>= 1) ss += __shfl_xor_sync(0xffffffffu, ss, o);
    if (lane == 0) s_s[warp] = ss;
    if (tid < T1) s_sc[tid] = e_;
    __syncthreads();
    float total = 0.0f;
#pragma unroll
    for (int w = 0; w < 8; w++) total += s_s[w];
    float inv = 1.0f / total;

    // context[e] = (1/total) * sum_t e_[t]*x[b,t,e]  -- 4 independent accumulators
    float a0 = 0.f, a1 = 0.f, a2 = 0.f, a3 = 0.f;
    const float* xb = x + (size_t)b * T1 * 256 + tid;
    int t = 0;
#pragma unroll 2
    for (; t + 4 <= T1; t += 4) {
        a0 = fmaf(s_sc[t + 0], xb[(size_t)(t + 0) * 256], a0);
        a1 = fmaf(s_sc[t + 1], xb[(size_t)(t + 1) * 256], a1);
        a2 = fmaf(s_sc[t + 2], xb[(size_t)(t + 2) * 256], a2);
        a3 = fmaf(s_sc[t + 3], xb[(size_t)(t + 3) * 256], a3);
    }
    for (; t < T1; t++) a0 = fmaf(s_sc[t], xb[(size_t)t * 256], a0);
    float ctx = ((a0 + a1) + (a2 + a3)) * inv;
    g_context[b * 256 + tid] = ctx;

    // y_tilde[b]
    float yv = ctx * fcw[tid];
#pragma unroll
    for (int o = 16; o; o >>= 1) yv += __shfl_xor_sync(0xffffffffu, yv, o);
    if (lane == 0) s_y[warp] = yv;
    __syncthreads();
    if (tid == 0) {
        float tot = 0.0f;
#pragma unroll
        for (int w = 0; w < 8; w++) tot += s_y[w];
        s_yt = tot + yh[b * T1 + s] * fcw[256] + fcb[0];
    }
    __syncthreads();
    float yt = s_yt;
    if (tid == 0) g_ytilde[b] = yt;

    // LSTM layer 0 pointwise: gates = gates_whh0(+biases) + yt*wih0
    const int u = tid;
    const float* gb = &g_gates[(size_t)b * G4];
    float gi = fmaf(yt, wih0[0 * 256 + u], gb[0 * 256 + u]);
    float gf = fmaf(yt, wih0[1 * 256 + u], gb[1 * 256 + u]);
    float gg = fmaf(yt, wih0[2 * 256 + u], gb[2 * 256 + u]);
    float go = fmaf(yt, wih0[3 * 256 + u], gb[3 * 256 + u]);
    float co = g_c[b * 256 + u];
    float cn = sigf(gf) * co + sigf(gi) * tanh_ex(gg);
    float hn = sigf(go) * tanh_ex(cn);
    g_c[b * 256 + u] = cn;
    g_h[b * 256 + u] = hn;
}

// ---------------- kernel K4/K5: LSTM layer l (l=1,2): Wih GEMM + cell update ----------------
__global__ __launch_bounds__(256) void lstm_layer_kernel(
    const float* __restrict__ wihr, int l)
{
    __shared__ float xs[32][34];
    __shared__ float ws[4][32][34];

    const int b0 = blockIdx.x * 32;
    const int u0 = blockIdx.y * 32;
    const int tid = threadIdx.x;
    const int tx = tid & 15, ty = tid >> 4;
    const int ul = tx * 2, bl = ty * 2;

    const float* hin = g_h + (l - 1) * BH;
    const float* Wih = wihr + (size_t)(l - 1) * G4 * HH;

    float2 acc[2][4];
#pragma unroll
    for (int i = 0; i < 2; i++)
#pragma unroll
        for (int g = 0; g < 4; g++) acc[i][g] = make_float2(0.f, 0.f);

    const int ldb = tid >> 3, ldk = (tid & 7) * 4;
    for (int kc = 0; kc < 256; kc += 32) {
        {
            float4 v = *(const float4*)&hin[(size_t)(b0 + ldb) * 256 + kc + ldk];
            xs[ldk + 0][ldb] = v.x; xs[ldk + 1][ldb] = v.y;
            xs[ldk + 2][ldb] = v.z; xs[ldk + 3][ldb] = v.w;
        }
#pragma unroll
        for (int i = tid; i < 1024; i += 256) {
            int g = i >> 8, u = (i >> 3) & 31, kq = (i & 7) * 4;
            float4 v = *(const float4*)&Wih[(size_t)((g << 8) + u0 + u) * 256 + kc + kq];
            ws[g][kq + 0][u] = v.x; ws[g][kq + 1][u] = v.y;
            ws[g][kq + 2][u] = v.z; ws[g][kq + 3][u] = v.w;
        }
        __syncthreads();
#pragma unroll
        for (int kk = 0; kk < 32; kk++) {
            float2 a = *(const float2*)&xs[kk][bl];
            float2 ax = make_float2(a.x, a.x);
            float2 ay = make_float2(a.y, a.y);
#pragma unroll
            for (int g = 0; g < 4; g++) {
                float2 w = *(const float2*)&ws[g][kk][ul];
                acc[0][g] = ffma2(ax, w, acc[0][g]);
                acc[1][g] = ffma2(ay, w, acc[1][g]);
            }
        }
        __syncthreads();
    }

#pragma unroll
    for (int i = 0; i < 2; i++) {
#pragma unroll
        for (int j = 0; j < 2; j++) {
            int b = b0 + bl + i;
            int u = u0 + ul + j;
            const float* gb = &g_gates[((size_t)l * BB + b) * G4];
            float gi = (j ? acc[i][0].y : acc[i][0].x) + gb[0 * 256 + u];
            float gf = (j ? acc[i][1].y : acc[i][1].x) + gb[1 * 256 + u];
            float gg = (j ? acc[i][2].y : acc[i][2].x) + gb[2 * 256 + u];
            float go = (j ? acc[i][3].y : acc[i][3].x) + gb[3 * 256 + u];
            float co = g_c[l * BH + b * 256 + u];
            float cn = sigf(gf) * co + sigf(gi) * tanh_ex(gg);
            float hn = sigf(go) * tanh_ex(cn);
            g_c[l * BH + b * 256 + u] = cn;
            g_h[l * BH + b * 256 + u] = hn;
        }
    }
}

// ---------------- kernel 6: final projection ----------------
__global__ __launch_bounds__(256) void final_kernel(
    const float* __restrict__ fcfw, const float* __restrict__ fcfb,
    float* __restrict__ out)
{
    const int b = blockIdx.x;
    const int tid = threadIdx.x;
    const int warp = tid >> 5, lane = tid & 31;
    __shared__ float s_r[8];

    float v = g_h[b * 256 + tid] * fcfw[tid]
            + g_context[b * 256 + tid] * fcfw[256 + tid];
#pragma unroll
    for (int o = 16; o; o >>= 1) v += __shfl_xor_sync(0xffffffffu, v, o);
    if (lane == 0) s_r[warp] = v;
    __syncthreads();
    if (tid == 0) {
        float tot = 0.0f;
#pragma unroll
        for (int w = 0; w < 8; w++) tot += s_r[w];
        out[b] = tot + fcfb[0];
    }
}

// ---------------- host launcher ----------------
extern "C" void kernel_launch(void* const* d_in, const int* in_sizes, int n_in,
                              void* d_out, int out_size)
{
    const float* x    = (const float*)d_in[0];
    const float* yh   = (const float*)d_in[1];
    const float* w1   = (const float*)d_in[2];
    const float* b1   = (const float*)d_in[3];
    const float* w2   = (const float*)d_in[4];
    const float* wih0 = (const float*)d_in[6];
    const float* wihr = (const float*)d_in[7];
    const float* whh  = (const float*)d_in[8];
    const float* bih  = (const float*)d_in[9];
    const float* bhh  = (const float*)d_in[10];
    const float* fcw  = (const float*)d_in[11];
    const float* fcb  = (const float*)d_in[12];
    const float* fcfw = (const float*)d_in[13];
    const float* fcfb = (const float*)d_in[14];
    float* out = (float*)d_out;

    zero_state_kernel<<<(NL * BH + 255) / 256, 256>>>();
    encproj_kernel<<<dim3(1016, 4), 256>>>(x, w1, b1);

    for (int s = 0; s < T1; s++) {
        fused_gemm_kernel<<<416, 256>>>(w1, whh, bih, bhh);
        scores_kernel<<<dim3(BB, 4), 256>>>(w2);
        attn_finish_kernel<<<BB, 256>>>(x, fcw, fcb, yh, wih0, s);
        lstm_layer_kernel<<<dim3(16, 8), 256>>>(wihr, 1);
        lstm_layer_kernel<<<dim3(16, 8), 256>>>(wihr, 2);
    }

    final_kernel<<<BB, 256>>>(fcfw, fcfb, out);
}